// round 9
// baseline (speedup 1.0000x reference)
#include <cuda_runtime.h>
#include <cuda_bf16.h>
#include <cstdint>

// Problem constants
#define NV     100000
#define DIN    512
#define DOUT   512
#define NC     4096
#define KPC    32      // vars per cluster
#define NE     16384   // edges
#define NS     16      // shared vars per edge
#define NEG_SLOPE 0.2f
#define CAP    64      // max edge contributions tracked per variable

// Scratch (device globals; no allocation allowed)
__device__ float g_feats[NC * DIN];     // 8 MB
__device__ float g_Q[NC * DOUT];        // 8 MB
__device__ float g_K[NC * DOUT];        // 8 MB
__device__ float g_V[NC * DOUT];        // 8 MB
__device__ float g_attn[NE];            // 64 KB
__device__ int   g_count[NV];           // 400 KB (zero-init; gather re-zeros)
__device__ int   g_list[(size_t)NV * CAP]; // 25.6 MB

// ===========================================================================
// Kernel 1: per-cluster mean pooling (at DRAM roofline)
// ===========================================================================
__global__ __launch_bounds__(128) void pool_kernel(
    const float* __restrict__ x, const int* __restrict__ ids)
{
    const int c = blockIdx.x;
    const int t = threadIdx.x;
    __shared__ int s_ids[KPC];
    if (t < KPC) s_ids[t] = ids[c * KPC + t];
    __syncthreads();

    float4 acc = make_float4(0.f, 0.f, 0.f, 0.f);
#pragma unroll 4
    for (int k = 0; k < KPC; k++) {
        const float4 v = reinterpret_cast<const float4*>(
            x + (size_t)s_ids[k] * DIN)[t];
        acc.x += v.x; acc.y += v.y; acc.z += v.z; acc.w += v.w;
    }
    const float inv = 1.0f / (float)KPC;
    acc.x *= inv; acc.y *= inv; acc.z *= inv; acc.w *= inv;
    reinterpret_cast<float4*>(g_feats + (size_t)c * DIN)[t] = acc;
}

// ===========================================================================
// Kernel 2: tf32 mma.sync GEMM, 64x64 warp tiles (known-good R8 version).
// CTA tile 128x128x32, 128 thr = 4 warps (2m x 2n), warp tile 64x64.
// ===========================================================================
#define BM 128
#define BN 128
#define BK 32
#define SSTRIDE 36

__device__ __forceinline__ uint32_t f32_to_tf32(float f)
{
    uint32_t u;
    asm("cvt.rna.tf32.f32 %0, %1;" : "=r"(u) : "f"(f));
    return u;
}

__device__ __forceinline__ void mma_tf32(
    float& d0, float& d1, float& d2, float& d3,
    uint32_t a0, uint32_t a1, uint32_t a2, uint32_t a3,
    uint32_t b0, uint32_t b1)
{
    asm volatile(
        "mma.sync.aligned.m16n8k8.row.col.f32.tf32.tf32.f32 "
        "{%0,%1,%2,%3}, {%4,%5,%6,%7}, {%8,%9}, {%0,%1,%2,%3};"
        : "+f"(d0), "+f"(d1), "+f"(d2), "+f"(d3)
        : "r"(a0), "r"(a1), "r"(a2), "r"(a3), "r"(b0), "r"(b1));
}

__global__ __launch_bounds__(128) void gemm_tc_kernel(
    const float* __restrict__ WQ, const float* __restrict__ WK,
    const float* __restrict__ WV)
{
    __shared__ uint32_t As[BM * SSTRIDE];
    __shared__ uint32_t Bs[BN * SSTRIDE];

    const float* Bsrc;
    float* C;
    if      (blockIdx.z == 0) { Bsrc = WQ; C = g_Q; }
    else if (blockIdx.z == 1) { Bsrc = WK; C = g_K; }
    else                      { Bsrc = WV; C = g_V; }
    const float* A = g_feats;

    const int tid  = threadIdx.x;
    const int wid  = tid >> 5;
    const int lane = tid & 31;
    const int bm = blockIdx.y * BM;
    const int bn = blockIdx.x * BN;

    const int warp_m = (wid >> 1) * 64;   // 0 or 64
    const int warp_n = (wid & 1) * 64;    // 0 or 64

    const int lr = lane >> 2;             // 0..7
    const int lc = lane & 3;              // 0..3

    float acc[4][8][4];
#pragma unroll
    for (int i = 0; i < 4; i++)
#pragma unroll
        for (int j = 0; j < 8; j++)
#pragma unroll
            for (int r = 0; r < 4; r++) acc[i][j][r] = 0.f;

    for (int k0 = 0; k0 < DIN; k0 += BK) {
#pragma unroll
        for (int i = 0; i < 8; i++) {
            const int q   = tid + i * 128;     // 0..1023 float4 slots
            const int row = q >> 3;            // 0..127
            const int kq  = (q & 7) * 4;       // 0..28
            const float4 a = *reinterpret_cast<const float4*>(
                A + (size_t)(bm + row) * DIN + k0 + kq);
            uint4 ua;
            ua.x = f32_to_tf32(a.x); ua.y = f32_to_tf32(a.y);
            ua.z = f32_to_tf32(a.z); ua.w = f32_to_tf32(a.w);
            *reinterpret_cast<uint4*>(&As[row * SSTRIDE + kq]) = ua;
            const float4 b = *reinterpret_cast<const float4*>(
                Bsrc + (size_t)(bn + row) * DIN + k0 + kq);
            uint4 ub;
            ub.x = f32_to_tf32(b.x); ub.y = f32_to_tf32(b.y);
            ub.z = f32_to_tf32(b.z); ub.w = f32_to_tf32(b.w);
            *reinterpret_cast<uint4*>(&Bs[row * SSTRIDE + kq]) = ub;
        }
        __syncthreads();

#pragma unroll
        for (int ks = 0; ks < 4; ks++) {
            const int kk = ks * 8;
            uint32_t af[4][4];
#pragma unroll
            for (int mf = 0; mf < 4; mf++) {
                const int rbase = (warp_m + mf * 16 + lr) * SSTRIDE + kk + lc;
                af[mf][0] = As[rbase];
                af[mf][1] = As[rbase + 8 * SSTRIDE];
                af[mf][2] = As[rbase + 4];
                af[mf][3] = As[rbase + 8 * SSTRIDE + 4];
            }
            uint32_t bf[8][2];
#pragma unroll
            for (int nf = 0; nf < 8; nf++) {
                const int rbase = (warp_n + nf * 8 + lr) * SSTRIDE + kk + lc;
                bf[nf][0] = Bs[rbase];
                bf[nf][1] = Bs[rbase + 4];
            }
#pragma unroll
            for (int mf = 0; mf < 4; mf++)
#pragma unroll
                for (int nf = 0; nf < 8; nf++)
                    mma_tf32(acc[mf][nf][0], acc[mf][nf][1],
                             acc[mf][nf][2], acc[mf][nf][3],
                             af[mf][0], af[mf][1], af[mf][2], af[mf][3],
                             bf[nf][0], bf[nf][1]);
        }
        __syncthreads();
    }

#pragma unroll
    for (int mf = 0; mf < 4; mf++) {
#pragma unroll
        for (int nf = 0; nf < 8; nf++) {
            const int row = bm + warp_m + mf * 16 + lr;
            const int col = bn + warp_n + nf * 8 + lc * 2;
            float2 v0 = make_float2(acc[mf][nf][0], acc[mf][nf][1]);
            float2 v1 = make_float2(acc[mf][nf][2], acc[mf][nf][3]);
            *reinterpret_cast<float2*>(C + (size_t)row * DOUT + col) = v0;
            *reinterpret_cast<float2*>(C + (size_t)(row + 8) * DOUT + col) = v1;
        }
    }
}

// ===========================================================================
// Kernel 3: per-edge attention score -> g_attn.  One warp per edge.
// (L2-bound at ~6.2 TB/s effective — at the LTS cap, leave alone.)
// ===========================================================================
__global__ __launch_bounds__(256) void attn_kernel(
    const int* __restrict__ edge_index,
    const float* __restrict__ head_weights,
    const int* __restrict__ active_heads)
{
    const int e = (blockIdx.x * blockDim.x + threadIdx.x) >> 5;
    if (e >= NE) return;
    const int lane = threadIdx.x & 31;

    const int c1 = edge_index[e];
    const int c2 = edge_index[NE + e];
    const float4* Q4 = reinterpret_cast<const float4*>(g_Q + (size_t)c1 * DOUT);
    const float4* K4 = reinterpret_cast<const float4*>(g_K + (size_t)c2 * DOUT);

    float p = 0.f;
#pragma unroll
    for (int j = 0; j < 4; j++) {
        const float4 q = Q4[lane + 32 * j];
        const float4 k = K4[lane + 32 * j];
        p += q.x * k.x + q.y * k.y + q.z * k.z + q.w * k.w;
    }
#pragma unroll
    for (int off = 16; off > 0; off >>= 1)
        p += __shfl_xor_sync(0xFFFFFFFFu, p, off);

    if (lane == 0) {
        float s = p * rsqrtf((float)DOUT);
        s = (s >= 0.f) ? s : NEG_SLOPE * s;
        const float sig = 1.0f / (1.0f + __expf(-s));
        const int ah = active_heads[0];
        float hm = 0.f;
        for (int i = 0; i < ah; i++) hm += head_weights[i];
        hm /= (float)ah;
        g_attn[e] = sig * hm;
    }
}

// ===========================================================================
// Kernel 4: build var -> edge incidence lists (counters zero at launch start)
// ===========================================================================
__global__ void build_list_kernel(const int* __restrict__ shared_vars)
{
    const int idx = blockIdx.x * blockDim.x + threadIdx.x;
    if (idx >= NE * NS) return;
    const int v = shared_vars[idx];
    const int e = idx >> 4;          // NS = 16
    const int pos = atomicAdd(&g_count[v], 1);
    if (pos < CAP) g_list[(size_t)v * CAP + pos] = e;
}

// ===========================================================================
// Kernel 5: gather. x_out[v] = x_var[v] + sum attn[e] * V[c2[e]]
// - x row read issued FIRST (hides metadata latency chain)
// - __ldcs / __stcs on the 410MB single-use stream (protects L2 for V + meta)
// - accumulate loop unrolled x2 with dual accumulators (V-load MLP)
// - resets g_count[v] after read (zero-at-launch-start invariant)
// ===========================================================================
__global__ __launch_bounds__(128) void gather_kernel(
    const float* __restrict__ x,
    const int* __restrict__ edge_index,
    float* __restrict__ x_out)
{
    const int v = blockIdx.x;
    const int t = threadIdx.x;

    // start the streaming x read immediately (evict-first: single-use data)
    const float4 xrow = __ldcs(
        reinterpret_cast<const float4*>(x + (size_t)v * DIN) + t);

    int cnt = g_count[v];
    if (cnt > CAP) cnt = CAP;

    __shared__ float s_a[CAP];
    __shared__ int   s_c[CAP];
    if (t < cnt) {
        const int e = g_list[(size_t)v * CAP + t];
        s_a[t] = g_attn[e];
        s_c[t] = edge_index[NE + e];
    }
    __syncthreads();
    if (t == 0) g_count[v] = 0;   // reset for next launch

    float4 acc0 = xrow;
    float4 acc1 = make_float4(0.f, 0.f, 0.f, 0.f);

    int i = 0;
    for (; i + 2 <= cnt; i += 2) {
        const float a0 = s_a[i];
        const float a1 = s_a[i + 1];
        const float4 w0 = reinterpret_cast<const float4*>(
            g_V + (size_t)s_c[i] * DOUT)[t];
        const float4 w1 = reinterpret_cast<const float4*>(
            g_V + (size_t)s_c[i + 1] * DOUT)[t];
        acc0.x += a0 * w0.x; acc0.y += a0 * w0.y;
        acc0.z += a0 * w0.z; acc0.w += a0 * w0.w;
        acc1.x += a1 * w1.x; acc1.y += a1 * w1.y;
        acc1.z += a1 * w1.z; acc1.w += a1 * w1.w;
    }
    if (i < cnt) {
        const float a0 = s_a[i];
        const float4 w0 = reinterpret_cast<const float4*>(
            g_V + (size_t)s_c[i] * DOUT)[t];
        acc0.x += a0 * w0.x; acc0.y += a0 * w0.y;
        acc0.z += a0 * w0.z; acc0.w += a0 * w0.w;
    }
    acc0.x += acc1.x; acc0.y += acc1.y;
    acc0.z += acc1.z; acc0.w += acc1.w;

    __stcs(reinterpret_cast<float4*>(x_out + (size_t)v * DIN) + t, acc0);
}

// ===========================================================================
// Launch — single stream, linear graph
// ===========================================================================
extern "C" void kernel_launch(void* const* d_in, const int* in_sizes, int n_in,
                              void* d_out, int out_size)
{
    const float* x_var        = (const float*)d_in[0];
    const float* W_Q          = (const float*)d_in[1];
    const float* W_K          = (const float*)d_in[2];
    const float* W_V          = (const float*)d_in[3];
    const float* head_weights = (const float*)d_in[4];
    const int*   cluster_ids  = (const int*)d_in[5];
    const int*   edge_index   = (const int*)d_in[6];
    const int*   shared_vars  = (const int*)d_in[7];
    const int*   active_heads = (const int*)d_in[8];
    float*       x_out        = (float*)d_out;

    build_list_kernel<<<(NE * NS + 255) / 256, 256>>>(shared_vars);
    pool_kernel<<<NC, 128>>>(x_var, cluster_ids);

    dim3 ggrid(DOUT / BN, NC / BM, 3);
    gemm_tc_kernel<<<ggrid, 128>>>(W_Q, W_K, W_V);

    attn_kernel<<<(NE * 32 + 255) / 256, 256>>>(edge_index, head_weights,
                                                active_heads);

    gather_kernel<<<NV, 128>>>(x_var, edge_index, x_out);
}

// round 10
// speedup vs baseline: 1.1569x; 1.1569x over previous
#include <cuda_runtime.h>
#include <cuda_bf16.h>
#include <cstdint>

// Problem constants
#define NV     100000
#define DIN    512
#define DOUT   512
#define NC     4096
#define KPC    32      // vars per cluster
#define NE     16384   // edges
#define NS     16      // shared vars per edge
#define NEG_SLOPE 0.2f
#define CAP    64      // max edge contributions tracked per variable

// Scratch (device globals; no allocation allowed)
__device__ float          g_feats[NC * DIN];   // 8 MB
__device__ float          g_Q[NC * DOUT];      // 8 MB
__device__ float          g_K[NC * DOUT];      // 8 MB
__device__ __nv_bfloat16  g_Vh[NC * DOUT];     // 4 MB (bf16 V for gather)
__device__ float          g_attn[NE];          // 64 KB
__device__ int            g_count[NV];         // zero-init; gather re-zeros
__device__ int            g_list[(size_t)NV * CAP]; // 25.6 MB

// ===========================================================================
// Kernel 1: per-cluster mean pooling (at DRAM roofline)
// ===========================================================================
__global__ __launch_bounds__(128) void pool_kernel(
    const float* __restrict__ x, const int* __restrict__ ids)
{
    const int c = blockIdx.x;
    const int t = threadIdx.x;
    __shared__ int s_ids[KPC];
    if (t < KPC) s_ids[t] = ids[c * KPC + t];
    __syncthreads();

    float4 acc = make_float4(0.f, 0.f, 0.f, 0.f);
#pragma unroll 4
    for (int k = 0; k < KPC; k++) {
        const float4 v = reinterpret_cast<const float4*>(
            x + (size_t)s_ids[k] * DIN)[t];
        acc.x += v.x; acc.y += v.y; acc.z += v.z; acc.w += v.w;
    }
    const float inv = 1.0f / (float)KPC;
    acc.x *= inv; acc.y *= inv; acc.z *= inv; acc.w *= inv;
    reinterpret_cast<float4*>(g_feats + (size_t)c * DIN)[t] = acc;
}

// ===========================================================================
// Kernel 2: tf32 mma.sync GEMM, 64x64 warp tiles (known-good R8 mainloop).
// z in {0,1}: fp32 out to g_Q/g_K.  z==2: bf16 out to g_Vh.
// ===========================================================================
#define BM 128
#define BN 128
#define BK 32
#define SSTRIDE 36

__device__ __forceinline__ uint32_t f32_to_tf32(float f)
{
    uint32_t u;
    asm("cvt.rna.tf32.f32 %0, %1;" : "=r"(u) : "f"(f));
    return u;
}

__device__ __forceinline__ void mma_tf32(
    float& d0, float& d1, float& d2, float& d3,
    uint32_t a0, uint32_t a1, uint32_t a2, uint32_t a3,
    uint32_t b0, uint32_t b1)
{
    asm volatile(
        "mma.sync.aligned.m16n8k8.row.col.f32.tf32.tf32.f32 "
        "{%0,%1,%2,%3}, {%4,%5,%6,%7}, {%8,%9}, {%0,%1,%2,%3};"
        : "+f"(d0), "+f"(d1), "+f"(d2), "+f"(d3)
        : "r"(a0), "r"(a1), "r"(a2), "r"(a3), "r"(b0), "r"(b1));
}

__global__ __launch_bounds__(128) void gemm_tc_kernel(
    const float* __restrict__ WQ, const float* __restrict__ WK,
    const float* __restrict__ WV)
{
    __shared__ uint32_t As[BM * SSTRIDE];
    __shared__ uint32_t Bs[BN * SSTRIDE];

    const float* Bsrc;
    float* C = nullptr;
    if      (blockIdx.z == 0) { Bsrc = WQ; C = g_Q; }
    else if (blockIdx.z == 1) { Bsrc = WK; C = g_K; }
    else                      { Bsrc = WV; }
    const float* A = g_feats;

    const int tid  = threadIdx.x;
    const int wid  = tid >> 5;
    const int lane = tid & 31;
    const int bm = blockIdx.y * BM;
    const int bn = blockIdx.x * BN;

    const int warp_m = (wid >> 1) * 64;   // 0 or 64
    const int warp_n = (wid & 1) * 64;    // 0 or 64

    const int lr = lane >> 2;             // 0..7
    const int lc = lane & 3;              // 0..3

    float acc[4][8][4];
#pragma unroll
    for (int i = 0; i < 4; i++)
#pragma unroll
        for (int j = 0; j < 8; j++)
#pragma unroll
            for (int r = 0; r < 4; r++) acc[i][j][r] = 0.f;

    for (int k0 = 0; k0 < DIN; k0 += BK) {
#pragma unroll
        for (int i = 0; i < 8; i++) {
            const int q   = tid + i * 128;     // 0..1023 float4 slots
            const int row = q >> 3;            // 0..127
            const int kq  = (q & 7) * 4;       // 0..28
            const float4 a = *reinterpret_cast<const float4*>(
                A + (size_t)(bm + row) * DIN + k0 + kq);
            uint4 ua;
            ua.x = f32_to_tf32(a.x); ua.y = f32_to_tf32(a.y);
            ua.z = f32_to_tf32(a.z); ua.w = f32_to_tf32(a.w);
            *reinterpret_cast<uint4*>(&As[row * SSTRIDE + kq]) = ua;
            const float4 b = *reinterpret_cast<const float4*>(
                Bsrc + (size_t)(bn + row) * DIN + k0 + kq);
            uint4 ub;
            ub.x = f32_to_tf32(b.x); ub.y = f32_to_tf32(b.y);
            ub.z = f32_to_tf32(b.z); ub.w = f32_to_tf32(b.w);
            *reinterpret_cast<uint4*>(&Bs[row * SSTRIDE + kq]) = ub;
        }
        __syncthreads();

#pragma unroll
        for (int ks = 0; ks < 4; ks++) {
            const int kk = ks * 8;
            uint32_t af[4][4];
#pragma unroll
            for (int mf = 0; mf < 4; mf++) {
                const int rbase = (warp_m + mf * 16 + lr) * SSTRIDE + kk + lc;
                af[mf][0] = As[rbase];
                af[mf][1] = As[rbase + 8 * SSTRIDE];
                af[mf][2] = As[rbase + 4];
                af[mf][3] = As[rbase + 8 * SSTRIDE + 4];
            }
            uint32_t bf[8][2];
#pragma unroll
            for (int nf = 0; nf < 8; nf++) {
                const int rbase = (warp_n + nf * 8 + lr) * SSTRIDE + kk + lc;
                bf[nf][0] = Bs[rbase];
                bf[nf][1] = Bs[rbase + 4];
            }
#pragma unroll
            for (int mf = 0; mf < 4; mf++)
#pragma unroll
                for (int nf = 0; nf < 8; nf++)
                    mma_tf32(acc[mf][nf][0], acc[mf][nf][1],
                             acc[mf][nf][2], acc[mf][nf][3],
                             af[mf][0], af[mf][1], af[mf][2], af[mf][3],
                             bf[nf][0], bf[nf][1]);
        }
        __syncthreads();
    }

    // epilogue: frag (row = lr [+8], col = 2*lc [+1])
    if (blockIdx.z < 2) {
#pragma unroll
        for (int mf = 0; mf < 4; mf++) {
#pragma unroll
            for (int nf = 0; nf < 8; nf++) {
                const int row = bm + warp_m + mf * 16 + lr;
                const int col = bn + warp_n + nf * 8 + lc * 2;
                float2 v0 = make_float2(acc[mf][nf][0], acc[mf][nf][1]);
                float2 v1 = make_float2(acc[mf][nf][2], acc[mf][nf][3]);
                *reinterpret_cast<float2*>(C + (size_t)row * DOUT + col) = v0;
                *reinterpret_cast<float2*>(C + (size_t)(row + 8) * DOUT + col) = v1;
            }
        }
    } else {
#pragma unroll
        for (int mf = 0; mf < 4; mf++) {
#pragma unroll
            for (int nf = 0; nf < 8; nf++) {
                const int row = bm + warp_m + mf * 16 + lr;
                const int col = bn + warp_n + nf * 8 + lc * 2;
                const __nv_bfloat162 h0 = __float22bfloat162_rn(
                    make_float2(acc[mf][nf][0], acc[mf][nf][1]));
                const __nv_bfloat162 h1 = __float22bfloat162_rn(
                    make_float2(acc[mf][nf][2], acc[mf][nf][3]));
                *reinterpret_cast<__nv_bfloat162*>(
                    g_Vh + (size_t)row * DOUT + col) = h0;
                *reinterpret_cast<__nv_bfloat162*>(
                    g_Vh + (size_t)(row + 8) * DOUT + col) = h1;
            }
        }
    }
}

// ===========================================================================
// Kernel 3: fused attn scores + incidence-list build.
// Blocks [0, 2048): one warp per edge -> g_attn.
// Blocks [2048, 3072): build var->edge lists (atomics).
// ===========================================================================
#define ATTN_BLOCKS ((NE * 32) / 256)            // 2048
#define BUILD_BLOCKS ((NE * NS + 255) / 256)     // 1024

__global__ __launch_bounds__(256) void attn_build_kernel(
    const int* __restrict__ edge_index,
    const float* __restrict__ head_weights,
    const int* __restrict__ active_heads,
    const int* __restrict__ shared_vars)
{
    if (blockIdx.x >= ATTN_BLOCKS) {
        // ---- incidence-list build branch ----
        const int idx = (blockIdx.x - ATTN_BLOCKS) * 256 + threadIdx.x;
        if (idx < NE * NS) {
            const int v = shared_vars[idx];
            const int e = idx >> 4;          // NS = 16
            const int pos = atomicAdd(&g_count[v], 1);
            if (pos < CAP) g_list[(size_t)v * CAP + pos] = e;
        }
        return;
    }

    // ---- attention branch: one warp per edge ----
    const int e = (blockIdx.x * 256 + threadIdx.x) >> 5;
    const int lane = threadIdx.x & 31;

    const int c1 = edge_index[e];
    const int c2 = edge_index[NE + e];
    const float4* Q4 = reinterpret_cast<const float4*>(g_Q + (size_t)c1 * DOUT);
    const float4* K4 = reinterpret_cast<const float4*>(g_K + (size_t)c2 * DOUT);

    float p = 0.f;
#pragma unroll
    for (int j = 0; j < 4; j++) {
        const float4 q = Q4[lane + 32 * j];
        const float4 k = K4[lane + 32 * j];
        p += q.x * k.x + q.y * k.y + q.z * k.z + q.w * k.w;
    }
#pragma unroll
    for (int off = 16; off > 0; off >>= 1)
        p += __shfl_xor_sync(0xFFFFFFFFu, p, off);

    if (lane == 0) {
        float s = p * rsqrtf((float)DOUT);
        s = (s >= 0.f) ? s : NEG_SLOPE * s;
        const float sig = 1.0f / (1.0f + __expf(-s));
        const int ah = active_heads[0];
        float hm = 0.f;
        for (int i = 0; i < ah; i++) hm += head_weights[i];
        hm /= (float)ah;
        g_attn[e] = sig * hm;
    }
}

// ===========================================================================
// Kernel 4: gather. x_out[v] = x_var[v] + sum attn[e] * Vh[c2[e]]  (bf16 V)
// One var per 128-thread block; thread t owns cols [4t, 4t+4).
// Resets g_count[v] after read (zero-at-launch-start invariant).
// ===========================================================================
__global__ __launch_bounds__(128) void gather_kernel(
    const float* __restrict__ x,
    const int* __restrict__ edge_index,
    float* __restrict__ x_out)
{
    const int v = blockIdx.x;
    const int t = threadIdx.x;

    const float4 xrow = __ldcs(
        reinterpret_cast<const float4*>(x + (size_t)v * DIN) + t);

    int cnt = g_count[v];
    if (cnt > CAP) cnt = CAP;

    __shared__ float s_a[CAP];
    __shared__ int   s_c[CAP];
    if (t < cnt) {
        const int e = g_list[(size_t)v * CAP + t];
        s_a[t] = g_attn[e];
        s_c[t] = edge_index[NE + e];
    }
    __syncthreads();
    if (t == 0) g_count[v] = 0;   // reset for next launch

    float4 acc0 = xrow;
    float4 acc1 = make_float4(0.f, 0.f, 0.f, 0.f);

    int i = 0;
    for (; i + 2 <= cnt; i += 2) {
        const float a0 = s_a[i];
        const float a1 = s_a[i + 1];
        const uint2 r0 = *reinterpret_cast<const uint2*>(
            g_Vh + (size_t)s_c[i] * DOUT + t * 4);
        const uint2 r1 = *reinterpret_cast<const uint2*>(
            g_Vh + (size_t)s_c[i + 1] * DOUT + t * 4);
        const float2 w0a = __bfloat1622float2(
            *reinterpret_cast<const __nv_bfloat162*>(&r0.x));
        const float2 w0b = __bfloat1622float2(
            *reinterpret_cast<const __nv_bfloat162*>(&r0.y));
        const float2 w1a = __bfloat1622float2(
            *reinterpret_cast<const __nv_bfloat162*>(&r1.x));
        const float2 w1b = __bfloat1622float2(
            *reinterpret_cast<const __nv_bfloat162*>(&r1.y));
        acc0.x += a0 * w0a.x; acc0.y += a0 * w0a.y;
        acc0.z += a0 * w0b.x; acc0.w += a0 * w0b.y;
        acc1.x += a1 * w1a.x; acc1.y += a1 * w1a.y;
        acc1.z += a1 * w1b.x; acc1.w += a1 * w1b.y;
    }
    if (i < cnt) {
        const float a0 = s_a[i];
        const uint2 r0 = *reinterpret_cast<const uint2*>(
            g_Vh + (size_t)s_c[i] * DOUT + t * 4);
        const float2 w0a = __bfloat1622float2(
            *reinterpret_cast<const __nv_bfloat162*>(&r0.x));
        const float2 w0b = __bfloat1622float2(
            *reinterpret_cast<const __nv_bfloat162*>(&r0.y));
        acc0.x += a0 * w0a.x; acc0.y += a0 * w0a.y;
        acc0.z += a0 * w0b.x; acc0.w += a0 * w0b.y;
    }
    acc0.x += acc1.x; acc0.y += acc1.y;
    acc0.z += acc1.z; acc0.w += acc1.w;

    __stcs(reinterpret_cast<float4*>(x_out + (size_t)v * DIN) + t, acc0);
}

// ===========================================================================
// Launch — single stream, linear graph, 4 kernels
// ===========================================================================
extern "C" void kernel_launch(void* const* d_in, const int* in_sizes, int n_in,
                              void* d_out, int out_size)
{
    const float* x_var        = (const float*)d_in[0];
    const float* W_Q          = (const float*)d_in[1];
    const float* W_K          = (const float*)d_in[2];
    const float* W_V          = (const float*)d_in[3];
    const float* head_weights = (const float*)d_in[4];
    const int*   cluster_ids  = (const int*)d_in[5];
    const int*   edge_index   = (const int*)d_in[6];
    const int*   shared_vars  = (const int*)d_in[7];
    const int*   active_heads = (const int*)d_in[8];
    float*       x_out        = (float*)d_out;

    pool_kernel<<<NC, 128>>>(x_var, cluster_ids);

    dim3 ggrid(DOUT / BN, NC / BM, 3);
    gemm_tc_kernel<<<ggrid, 128>>>(W_Q, W_K, W_V);

    attn_build_kernel<<<ATTN_BLOCKS + BUILD_BLOCKS, 256>>>(
        edge_index, head_weights, active_heads, shared_vars);

    gather_kernel<<<NV, 128>>>(x_var, edge_index, x_out);
}